// round 14
// baseline (speedup 1.0000x reference)
#include <cuda_runtime.h>
#include <cuda_fp16.h>
#include <cstdint>
#include <math.h>

// ----------------------------------------------------------------------------
// Problem constants
// ----------------------------------------------------------------------------
#define Bn   4
#define Sn   2048
#define Dn   1024
#define Hn   16
#define HDn  64
#define Mrows (Bn*Sn)          // 8192
#define D4   (4*Dn)            // 4096

// ----------------------------------------------------------------------------
// Scratch (device globals -- no allocations allowed)
// ----------------------------------------------------------------------------
__device__ __half g_qkv  [(size_t)Mrows * 3 * Dn];
__device__ __half g_hA   [(size_t)Mrows * Dn];
__device__ __half g_at   [(size_t)Mrows * Dn];
__device__ __half g_h1   [(size_t)Mrows * D4];
__device__ __half g_wqkvT[(size_t)3 * Dn * Dn];
__device__ __half g_woT  [(size_t)Dn * Dn];
__device__ __half g_w1T  [(size_t)D4 * Dn];
__device__ __half g_w2T  [(size_t)Dn * D4];
__device__ float  g_bp[3 * Dn];

__device__ __forceinline__ uint32_t smem_u32(const void* p) {
    uint32_t a;
    asm("{ .reg .u64 t; cvta.to.shared.u64 t, %1; cvt.u32.u64 %0, t; }" : "=r"(a) : "l"(p));
    return a;
}
__device__ __forceinline__ void cp_async16(void* dst, const void* src) {
    asm volatile("cp.async.cg.shared.global [%0], [%1], 16;"
                 :: "r"(smem_u32(dst)), "l"(src) : "memory");
}
#define CP_COMMIT() asm volatile("cp.async.commit_group;" ::: "memory")
#define CP_WAIT(n)  asm volatile("cp.async.wait_group %0;" :: "n"(n) : "memory")

__device__ __forceinline__ void ldsm_x4(uint32_t* r, uint32_t a) {
    asm volatile("ldmatrix.sync.aligned.m8n8.x4.shared.b16 {%0,%1,%2,%3}, [%4];"
                 : "=r"(r[0]), "=r"(r[1]), "=r"(r[2]), "=r"(r[3]) : "r"(a));
}
__device__ __forceinline__ void ldsm_x4_t(uint32_t* r, uint32_t a) {
    asm volatile("ldmatrix.sync.aligned.m8n8.x4.trans.shared.b16 {%0,%1,%2,%3}, [%4];"
                 : "=r"(r[0]), "=r"(r[1]), "=r"(r[2]), "=r"(r[3]) : "r"(a));
}
__device__ __forceinline__ void mma16816(float* d, const uint32_t* a, const uint32_t* b) {
    asm volatile("mma.sync.aligned.m16n8k16.row.col.f32.f16.f16.f32 "
                 "{%0,%1,%2,%3}, {%4,%5,%6,%7}, {%8,%9}, {%0,%1,%2,%3};"
                 : "+f"(d[0]), "+f"(d[1]), "+f"(d[2]), "+f"(d[3])
                 : "r"(a[0]), "r"(a[1]), "r"(a[2]), "r"(a[3]), "r"(b[0]), "r"(b[1]));
}

// ----------------------------------------------------------------------------
// Fused QKV transpose+pack (+ bias pack on z==48)
// ----------------------------------------------------------------------------
__global__ void qkv_pack_kernel(const float* __restrict__ Wq,
                                const float* __restrict__ Wk,
                                const float* __restrict__ Wv,
                                const float* __restrict__ bq,
                                const float* __restrict__ bk,
                                const float* __restrict__ bv,
                                __half* __restrict__ dst,
                                float* __restrict__ bp)
{
    __shared__ float t[32][33];
    int z = blockIdx.z;
    int tx = threadIdx.x, ty = threadIdx.y;
    if (z == 48) {
        int tid = ty * 32 + tx + blockIdx.x * 256 + blockIdx.y * 512;
        #pragma unroll
        for (int i = 0; i < 3; i++) {
            int idx = tid + i * 1024;
            if (idx < 3 * Dn) {
                int w = idx >> 10, c = idx & 1023;
                bp[idx] = (w == 0 ? bq : w == 1 ? bk : bv)[c];
            }
        }
        return;
    }
    int w = z >> 4, zh = z & 15;
    const float* src = (w == 0 ? Wq : w == 1 ? Wk : Wv) + (size_t)zh * Dn * HDn;
    int n0 = blockIdx.x * 32, k0 = blockIdx.y * 32;
    #pragma unroll
    for (int j = 0; j < 4; j++) {
        int k = k0 + ty + j * 8;
        t[ty + j * 8][tx] = src[(size_t)k * HDn + n0 + tx];
    }
    __syncthreads();
    int row_base = w * Dn + zh * HDn;
    #pragma unroll
    for (int j = 0; j < 4; j++) {
        int n = n0 + ty + j * 8;
        size_t o = (size_t)(row_base + n) * Dn + k0 + tx;
        dst[o] = __float2half_rn(t[tx][ty + j * 8]);
    }
}

__global__ void transpose_pack_kernel(const float* __restrict__ src,
                                      __half* __restrict__ dst,
                                      int Ks, int Ns)
{
    __shared__ float t[32][33];
    int n0 = blockIdx.x * 32, k0 = blockIdx.y * 32;
    int tx = threadIdx.x, ty = threadIdx.y;
    #pragma unroll
    for (int j = 0; j < 4; j++) {
        int k = k0 + ty + j * 8;
        t[ty + j * 8][tx] = src[(size_t)k * Ns + n0 + tx];
    }
    __syncthreads();
    #pragma unroll
    for (int j = 0; j < 4; j++) {
        int n = n0 + ty + j * 8;
        size_t o = (size_t)n * Ks + k0 + tx;
        dst[o] = __float2half_rn(t[tx][ty + j * 8]);
    }
}

// ----------------------------------------------------------------------------
// LayerNorm -> fp16.
// ----------------------------------------------------------------------------
__global__ void __launch_bounds__(256) ln_kernel(const float* __restrict__ X,
                                                 const float* __restrict__ gamma,
                                                 const float* __restrict__ beta,
                                                 __half* __restrict__ Y)
{
    int row = blockIdx.x;
    int tid = threadIdx.x;
    float4 xv = ((const float4*)(X + (size_t)row * Dn))[tid];

    __shared__ float red[8];
    float s = xv.x + xv.y + xv.z + xv.w;
    #pragma unroll
    for (int o = 16; o > 0; o >>= 1) s += __shfl_xor_sync(0xffffffffu, s, o);
    if ((tid & 31) == 0) red[tid >> 5] = s;
    __syncthreads();
    float mu = (red[0]+red[1]+red[2]+red[3]+red[4]+red[5]+red[6]+red[7]) * (1.0f / Dn);
    __syncthreads();

    float dx = xv.x - mu, dy = xv.y - mu, dz = xv.z - mu, dw = xv.w - mu;
    float sq = dx*dx + dy*dy + dz*dz + dw*dw;
    #pragma unroll
    for (int o = 16; o > 0; o >>= 1) sq += __shfl_xor_sync(0xffffffffu, sq, o);
    if ((tid & 31) == 0) red[tid >> 5] = sq;
    __syncthreads();
    float var = (red[0]+red[1]+red[2]+red[3]+red[4]+red[5]+red[6]+red[7]) * (1.0f / Dn);
    float inv = rsqrtf(var + 1e-5f);

    float4 gv = ((const float4*)gamma)[tid];
    float4 bv = ((const float4*)beta)[tid];
    float o0 = dx*inv*gv.x + bv.x, o1 = dy*inv*gv.y + bv.y;
    float o2 = dz*inv*gv.z + bv.z, o3 = dw*inv*gv.w + bv.w;

    size_t off = (size_t)row * Dn + tid * 4;
    *(__half2*)&Y[off]     = __floats2half2_rn(o0, o1);
    *(__half2*)&Y[off + 2] = __floats2half2_rn(o2, o3);
}

// ----------------------------------------------------------------------------
// Raw mma.sync fp16 GEMM (128x128 tile, 4 warps, 64x64 warp tile, BK=64,
// 2-stage, 3 CTAs/SM). Direct register->GMEM epilogue (32B-sector stores).
// ----------------------------------------------------------------------------
__device__ __forceinline__ float gelu_exact(float v) {
    return 0.5f * v * (1.0f + erff(v * 0.70710678118654752f));
}

#define BK     64
#define KPITCH 72
#define TILEB  (128 * KPITCH * 2)
#define STAGEB (2 * TILEB)
#define NSTAGE 2
#define GEMM_SMEM (NSTAGE * STAGEB)

template <bool GELU_, bool RES_, bool OUTF, bool OUTB>
__global__ void __launch_bounds__(128, 3) mma_gemm_kernel(
    const __half* __restrict__ A, const __half* __restrict__ B,
    const float* __restrict__ bias, const float* __restrict__ residual,
    float* __restrict__ Cf, __half* __restrict__ Ch,
    int N, int K)
{
    extern __shared__ __align__(128) char smem[];

    const int tid = threadIdx.x;
    const int wid = tid >> 5;
    const int lane = tid & 31;
    const int wm = wid >> 1;
    const int wn = wid & 1;
    const int bx = blockIdx.x, by = blockIdx.y;

    const size_t arow = (size_t)by * 128;
    const size_t brow = (size_t)bx * 128;

    auto load_chunk = [&](int kc, int st) {
        char* base = smem + st * STAGEB;
        __half* A_s = (__half*)(base);
        __half* B_s = (__half*)(base + TILEB);
        #pragma unroll
        for (int i = 0; i < 8; i++) {
            int idx = tid + i * 128;
            int row = idx >> 3, c = idx & 7;
            int so = row * KPITCH + c * 8;
            cp_async16(&A_s[so], A + (arow + row) * (size_t)K + kc * BK + c * 8);
            cp_async16(&B_s[so], B + (brow + row) * (size_t)K + kc * BK + c * 8);
        }
    };

    float acc[4][8][4];
    #pragma unroll
    for (int i = 0; i < 4; i++)
        #pragma unroll
        for (int n = 0; n < 8; n++)
            #pragma unroll
            for (int e = 0; e < 4; e++) acc[i][n][e] = 0.0f;

    const int a_r  = wm * 64 + (lane & 15);
    const int a_k  = (lane >> 4) << 3;
    const int b_r  = wn * 64 + ((lane >> 4) << 3) + (lane & 7);
    const int b_k  = ((lane >> 3) & 1) << 3;

    const int nk = K / BK;
    load_chunk(0, 0); CP_COMMIT();

    for (int kc = 0; kc < nk; kc++) {
        const int st = kc & 1;
        CP_WAIT(0);
        __syncthreads();
        if (kc + 1 < nk) { load_chunk(kc + 1, st ^ 1); CP_COMMIT(); }

        char* base = smem + st * STAGEB;
        const uint32_t uA = smem_u32(base);
        const uint32_t uB = smem_u32(base + TILEB);

        #pragma unroll
        for (int ks = 0; ks < BK / 16; ks++) {
            const int kof = ks * 16;
            uint32_t a[4][4];
            #pragma unroll
            for (int i = 0; i < 4; i++)
                ldsm_x4(a[i], uA + (uint32_t)(((a_r + i * 16) * KPITCH + kof + a_k) * 2));
            #pragma unroll
            for (int gp = 0; gp < 2; gp++) {
                uint32_t b[2][4];
                #pragma unroll
                for (int g = 0; g < 2; g++)
                    ldsm_x4(b[g], uB + (uint32_t)(((b_r + (gp * 2 + g) * 16) * KPITCH + kof + b_k) * 2));
                #pragma unroll
                for (int i = 0; i < 4; i++)
                    #pragma unroll
                    for (int nn = 0; nn < 4; nn++)
                        mma16816(acc[i][gp * 4 + nn], a[i], &b[nn >> 1][(nn & 1) * 2]);
            }
        }
    }

    // Direct epilogue: acc fragments -> GMEM (float2 / half2, 32B-sector coalesced)
    const int c_r = lane >> 2;           // row within 16-tile (second row = +8)
    const int c_c = (lane & 3) << 1;     // col pair within 8-col group
    float2 bb[8];
    #pragma unroll
    for (int n = 0; n < 8; n++)
        bb[n] = *(const float2*)&bias[bx * 128 + wn * 64 + n * 8 + c_c];
    #pragma unroll
    for (int i = 0; i < 4; i++) {
        size_t m0 = arow + wm * 64 + i * 16 + c_r;
        #pragma unroll
        for (int n = 0; n < 8; n++) {
            int c = bx * 128 + wn * 64 + n * 8 + c_c;
            float v0 = acc[i][n][0] + bb[n].x;
            float v1 = acc[i][n][1] + bb[n].y;
            float v2 = acc[i][n][2] + bb[n].x;
            float v3 = acc[i][n][3] + bb[n].y;
            if (GELU_) {
                v0 = gelu_exact(v0); v1 = gelu_exact(v1);
                v2 = gelu_exact(v2); v3 = gelu_exact(v3);
            }
            if (RES_) {
                float2 r0 = *(const float2*)&residual[m0 * N + c];
                float2 r1 = *(const float2*)&residual[(m0 + 8) * N + c];
                v0 += r0.x; v1 += r0.y; v2 += r1.x; v3 += r1.y;
            }
            if (OUTF) {
                *(float2*)&Cf[m0 * N + c]       = make_float2(v0, v1);
                *(float2*)&Cf[(m0 + 8) * N + c] = make_float2(v2, v3);
            }
            if (OUTB) {
                *(__half2*)&Ch[m0 * N + c]       = __floats2half2_rn(v0, v1);
                *(__half2*)&Ch[(m0 + 8) * N + c] = __floats2half2_rn(v2, v3);
            }
        }
    }
}

// ----------------------------------------------------------------------------
// 128x64-tile GEMM for N=1024 GEMMs (Wo, MLP2) -- 4 CTAs/SM. Direct epilogue.
// Always: +bias, +residual, fp32 out.
// ----------------------------------------------------------------------------
#define BTILE64B (64 * KPITCH * 2)
#define STAGE64B (TILEB + BTILE64B)
#define GEMM64_SMEM (2 * STAGE64B)

__global__ void __launch_bounds__(128, 4) mma_gemm64_kernel(
    const __half* __restrict__ A, const __half* __restrict__ B,
    const float* __restrict__ bias, const float* __restrict__ residual,
    float* __restrict__ Cf, int N, int K)
{
    extern __shared__ __align__(128) char smem[];

    const int tid = threadIdx.x;
    const int wid = tid >> 5;
    const int lane = tid & 31;
    const int wm = wid >> 1;
    const int wn = wid & 1;
    const int bx = blockIdx.x, by = blockIdx.y;

    const size_t arow = (size_t)by * 128;
    const size_t brow = (size_t)bx * 64;

    auto load_chunk = [&](int kc, int st) {
        char* base = smem + st * STAGE64B;
        __half* A_s = (__half*)(base);
        __half* B_s = (__half*)(base + TILEB);
        #pragma unroll
        for (int i = 0; i < 8; i++) {
            int idx = tid + i * 128;
            int row = idx >> 3, c = idx & 7;
            cp_async16(&A_s[row * KPITCH + c * 8],
                       A + (arow + row) * (size_t)K + kc * BK + c * 8);
        }
        #pragma unroll
        for (int i = 0; i < 4; i++) {
            int idx = tid + i * 128;
            int row = idx >> 3, c = idx & 7;
            cp_async16(&B_s[row * KPITCH + c * 8],
                       B + (brow + row) * (size_t)K + kc * BK + c * 8);
        }
    };

    float acc[4][4][4];
    #pragma unroll
    for (int i = 0; i < 4; i++)
        #pragma unroll
        for (int n = 0; n < 4; n++)
            #pragma unroll
            for (int e = 0; e < 4; e++) acc[i][n][e] = 0.0f;

    const int a_r  = wm * 64 + (lane & 15);
    const int a_k  = (lane >> 4) << 3;
    const int b_r  = wn * 32 + ((lane >> 4) << 3) + (lane & 7);
    const int b_k  = ((lane >> 3) & 1) << 3;

    const int nk = K / BK;
    load_chunk(0, 0); CP_COMMIT();

    for (int kc = 0; kc < nk; kc++) {
        const int st = kc & 1;
        CP_WAIT(0);
        __syncthreads();
        if (kc + 1 < nk) { load_chunk(kc + 1, st ^ 1); CP_COMMIT(); }

        char* base = smem + st * STAGE64B;
        const uint32_t uA = smem_u32(base);
        const uint32_t uB = smem_u32(base + TILEB);

        #pragma unroll
        for (int ks = 0; ks < BK / 16; ks++) {
            const int kof = ks * 16;
            uint32_t a[4][4], b[2][4];
            #pragma unroll
            for (int i = 0; i < 4; i++)
                ldsm_x4(a[i], uA + (uint32_t)(((a_r + i * 16) * KPITCH + kof + a_k) * 2));
            #pragma unroll
            for (int g = 0; g < 2; g++)
                ldsm_x4(b[g], uB + (uint32_t)(((b_r + g * 16) * KPITCH + kof + b_k) * 2));
            #pragma unroll
            for (int i = 0; i < 4; i++)
                #pragma unroll
                for (int nn = 0; nn < 4; nn++)
                    mma16816(acc[i][nn], a[i], &b[nn >> 1][(nn & 1) * 2]);
        }
    }

    // Direct epilogue (+bias +residual, fp32 out)
    const int c_r = lane >> 2;
    const int c_c = (lane & 3) << 1;
    float2 bb[4];
    #pragma unroll
    for (int n = 0; n < 4; n++)
        bb[n] = *(const float2*)&bias[bx * 64 + wn * 32 + n * 8 + c_c];
    #pragma unroll
    for (int i = 0; i < 4; i++) {
        size_t m0 = arow + wm * 64 + i * 16 + c_r;
        #pragma unroll
        for (int n = 0; n < 4; n++) {
            int c = bx * 64 + wn * 32 + n * 8 + c_c;
            float2 r0 = *(const float2*)&residual[m0 * N + c];
            float2 r1 = *(const float2*)&residual[(m0 + 8) * N + c];
            *(float2*)&Cf[m0 * N + c] =
                make_float2(acc[i][n][0] + bb[n].x + r0.x, acc[i][n][1] + bb[n].y + r0.y);
            *(float2*)&Cf[(m0 + 8) * N + c] =
                make_float2(acc[i][n][2] + bb[n].x + r1.x, acc[i][n][3] + bb[n].y + r1.y);
        }
    }
}

// ----------------------------------------------------------------------------
// Tensor-core flash attention: 256 threads, 128-query tile, heavy-tiles-first.
// exp2-folded softmax; per-warp skip of fully-masked diagonal tiles.
// ----------------------------------------------------------------------------
#define AQP 72
#define ATT_SMEM ((128 + 4 * 64) * AQP * 2)
#define C2 0.18033688011112042f    // 0.125 * log2(e)

__global__ void __launch_bounds__(256) attn_mma_kernel(const __half* __restrict__ QKV,
                                                       __half* __restrict__ O)
{
    extern __shared__ __align__(16) __half smh[];
    __half* Qs = smh;

    int qb = gridDim.x - 1 - blockIdx.x;        // heavy tiles scheduled first
    int bh = blockIdx.y;
    int b = bh >> 4, h = bh & 15;
    int tid = threadIdx.x, w = tid >> 5, lane = tid & 31;

    const size_t rowbase = (size_t)(b * Sn) * 3072 + (size_t)h * 64;

    #pragma unroll
    for (int i = 0; i < 4; i++) {
        int idx = tid + i * 256;
        int row = idx >> 3, c = idx & 7;
        cp_async16(&Qs[row * AQP + c * 8],
                   QKV + rowbase + (size_t)(qb * 128 + row) * 3072 + c * 8);
    }
    CP_COMMIT();

    auto load_kv = [&](int kb, int st) {
        __half* K_s = smh + (128 + 64 * st) * AQP;
        __half* V_s = smh + (128 + 64 * (2 + st)) * AQP;
        #pragma unroll
        for (int i = 0; i < 2; i++) {
            int idx = tid + i * 256;
            int row = idx >> 3, c = idx & 7;
            size_t src = rowbase + (size_t)(kb * 64 + row) * 3072 + c * 8;
            cp_async16(&K_s[row * AQP + c * 8], QKV + src + 1024);
            cp_async16(&V_s[row * AQP + c * 8], QKV + src + 2048);
        }
    };
    load_kv(0, 0); CP_COMMIT();
    CP_WAIT(0);
    __syncthreads();

    uint32_t aQ[4][4];
    {
        const uint32_t uQ = smem_u32(Qs);
        int a_r = w * 16 + (lane & 15);
        int a_k = (lane >> 4) << 3;
        #pragma unroll
        for (int t = 0; t < 4; t++)
            ldsm_x4(aQ[t], uQ + (uint32_t)((a_r * AQP + t * 16 + a_k) * 2));
    }

    const int bk_r = ((lane >> 4) << 3) + (lane & 7);
    const int bk_k = ((lane >> 3) & 1) << 3;
    const int bv_r = (((lane >> 3) & 1) << 3) + (lane & 7);
    const int bv_c = (lane >> 4) << 3;

    float o[8][4];
    #pragma unroll
    for (int j = 0; j < 8; j++)
        #pragma unroll
        for (int e = 0; e < 4; e++) o[j][e] = 0.0f;
    float m0 = -1e30f, m1 = -1e30f, l0 = 0.0f, l1 = 0.0f;

    const int wrow = qb * 128 + w * 16;
    const int qg0  = wrow + (lane >> 2);
    const int kb_end = 2 * qb + 1;

    for (int kb = 0; kb <= kb_end; kb++) {
        const int st = kb & 1;
        if (kb < kb_end) { load_kv(kb + 1, st ^ 1); CP_COMMIT(); }

        const bool full_skip = (kb * 64 > wrow + 15);
        if (!full_skip) {
            const uint32_t uK = smem_u32(smh + (128 + 64 * st) * AQP);
            const uint32_t uV = smem_u32(smh + (128 + 64 * (2 + st)) * AQP);

            float s[8][4];
            #pragma unroll
            for (int j = 0; j < 8; j++)
                #pragma unroll
                for (int e = 0; e < 4; e++) s[j][e] = 0.0f;
            #pragma unroll
            for (int t = 0; t < 4; t++) {
                uint32_t bK[4][4];
                #pragma unroll
                for (int g = 0; g < 4; g++)
                    ldsm_x4(bK[g], uK + (uint32_t)(((g * 16 + bk_r) * AQP + t * 16 + bk_k) * 2));
                #pragma unroll
                for (int j = 0; j < 8; j++)
                    mma16816(s[j], aQ[t], &bK[j >> 1][(j & 1) * 2]);
            }

            if (kb * 64 + 63 > wrow) {
                #pragma unroll
                for (int j = 0; j < 8; j++) {
                    int col = kb * 64 + j * 8 + (lane & 3) * 2;
                    if (col     > qg0)     s[j][0] = -1e30f;
                    if (col + 1 > qg0)     s[j][1] = -1e30f;
                    if (col     > qg0 + 8) s[j][2] = -1e30f;
                    if (col + 1 > qg0 + 8) s[j][3] = -1e30f;
                }
            }

            float ml0 = -1e30f, ml1 = -1e30f;
            #pragma unroll
            for (int j = 0; j < 8; j++) {
                ml0 = fmaxf(ml0, fmaxf(s[j][0], s[j][1]));
                ml1 = fmaxf(ml1, fmaxf(s[j][2], s[j][3]));
            }
            ml0 = fmaxf(ml0, __shfl_xor_sync(0xffffffffu, ml0, 1));
            ml0 = fmaxf(ml0, __shfl_xor_sync(0xffffffffu, ml0, 2));
            ml1 = fmaxf(ml1, __shfl_xor_sync(0xffffffffu, ml1, 1));
            ml1 = fmaxf(ml1, __shfl_xor_sync(0xffffffffu, ml1, 2));

            float mn0 = fmaxf(m0, ml0), mn1 = fmaxf(m1, ml1);
            float al0 = exp2f((m0 - mn0) * C2), al1 = exp2f((m1 - mn1) * C2);
            float mc0 = mn0 * C2, mc1 = mn1 * C2;

            float ls0 = 0.0f, ls1 = 0.0f;
            uint32_t pfrag[4][4];
            #pragma unroll
            for (int j = 0; j < 8; j++) {
                float p0 = exp2f(__fmaf_rn(s[j][0], C2, -mc0));
                float p1 = exp2f(__fmaf_rn(s[j][1], C2, -mc0));
                float p2 = exp2f(__fmaf_rn(s[j][2], C2, -mc1));
                float p3 = exp2f(__fmaf_rn(s[j][3], C2, -mc1));
                ls0 += p0 + p1; ls1 += p2 + p3;
                int t = j >> 1, hi = (j & 1) * 2;
                __half2 h01 = __floats2half2_rn(p0, p1);
                __half2 h23 = __floats2half2_rn(p2, p3);
                pfrag[t][hi]     = *(uint32_t*)&h01;
                pfrag[t][hi + 1] = *(uint32_t*)&h23;
            }
            ls0 += __shfl_xor_sync(0xffffffffu, ls0, 1);
            ls0 += __shfl_xor_sync(0xffffffffu, ls0, 2);
            ls1 += __shfl_xor_sync(0xffffffffu, ls1, 1);
            ls1 += __shfl_xor_sync(0xffffffffu, ls1, 2);

            l0 = l0 * al0 + ls0;  l1 = l1 * al1 + ls1;
            m0 = mn0;             m1 = mn1;
            #pragma unroll
            for (int j = 0; j < 8; j++) {
                o[j][0] *= al0; o[j][1] *= al0;
                o[j][2] *= al1; o[j][3] *= al1;
            }

            #pragma unroll
            for (int t = 0; t < 4; t++) {
                uint32_t bV[4][4];
                #pragma unroll
                for (int g = 0; g < 4; g++)
                    ldsm_x4_t(bV[g], uV + (uint32_t)(((t * 16 + bv_r) * AQP + g * 16 + bv_c) * 2));
                #pragma unroll
                for (int j = 0; j < 8; j++)
                    mma16816(o[j], pfrag[t], &bV[j >> 1][(j & 1) * 2]);
            }
        }

        if (kb < kb_end) CP_WAIT(0);
        __syncthreads();
    }

    float inv0 = 1.0f / l0, inv1 = 1.0f / l1;
    size_t ob = (size_t)(b * Sn + qb * 128 + w * 16 + (lane >> 2)) * Dn + h * 64;
    #pragma unroll
    for (int j = 0; j < 8; j++) {
        int col = j * 8 + (lane & 3) * 2;
        __half2 v0 = __floats2half2_rn(o[j][0] * inv0, o[j][1] * inv0);
        __half2 v1 = __floats2half2_rn(o[j][2] * inv1, o[j][3] * inv1);
        *(__half2*)&O[ob + col]           = v0;
        *(__half2*)&O[ob + 8 * Dn + col]  = v1;
    }
}

// ----------------------------------------------------------------------------
// Launch (pack(0), LN1(1), QKV GEMM(2), attention(3) <- profiled index)
// ----------------------------------------------------------------------------
extern "C" void kernel_launch(void* const* d_in, const int* in_sizes, int n_in,
                              void* d_out, int out_size)
{
    const float* x     = (const float*)d_in[0];
    const float* Wq    = (const float*)d_in[1];
    const float* Wk    = (const float*)d_in[2];
    const float* Wv    = (const float*)d_in[3];
    const float* bq    = (const float*)d_in[4];
    const float* bk    = (const float*)d_in[5];
    const float* bv    = (const float*)d_in[6];
    const float* Wo    = (const float*)d_in[7];
    const float* bo    = (const float*)d_in[8];
    const float* W1    = (const float*)d_in[9];
    const float* b1    = (const float*)d_in[10];
    const float* W2    = (const float*)d_in[11];
    const float* b2    = (const float*)d_in[12];
    const float* gamma = (const float*)d_in[13];
    const float* beta  = (const float*)d_in[14];
    float* out = (float*)d_out;

    float *bp;
    __half *qkv, *hA, *at, *h1, *wq, *wo, *w1, *w2;
    cudaGetSymbolAddress((void**)&qkv, g_qkv);
    cudaGetSymbolAddress((void**)&bp,  g_bp);
    cudaGetSymbolAddress((void**)&hA,  g_hA);
    cudaGetSymbolAddress((void**)&at,  g_at);
    cudaGetSymbolAddress((void**)&h1,  g_h1);
    cudaGetSymbolAddress((void**)&wq,  g_wqkvT);
    cudaGetSymbolAddress((void**)&wo,  g_woT);
    cudaGetSymbolAddress((void**)&w1,  g_w1T);
    cudaGetSymbolAddress((void**)&w2,  g_w2T);

    cudaFuncSetAttribute(mma_gemm_kernel<false, false, false, true >,
                         cudaFuncAttributeMaxDynamicSharedMemorySize, GEMM_SMEM);
    cudaFuncSetAttribute(mma_gemm_kernel<true,  false, false, true >,
                         cudaFuncAttributeMaxDynamicSharedMemorySize, GEMM_SMEM);
    cudaFuncSetAttribute(mma_gemm64_kernel,
                         cudaFuncAttributeMaxDynamicSharedMemorySize, GEMM64_SMEM);
    cudaFuncSetAttribute(attn_mma_kernel,
                         cudaFuncAttributeMaxDynamicSharedMemorySize, ATT_SMEM);

    dim3 tb(32, 8);
    // 0: fused QKV weight + bias pack
    qkv_pack_kernel<<<dim3(2, 32, 49), tb>>>(Wq, Wk, Wv, bq, bk, bv, wq, bp);
    // 1: LN1
    ln_kernel<<<Mrows, 256>>>(x, gamma, beta, hA);
    // 2: QKV GEMM -> fp16 qkv
    mma_gemm_kernel<false, false, false, true><<<dim3(3 * Dn / 128, Mrows / 128), 128, GEMM_SMEM>>>(
        hA, wq, bp, x, out, qkv, 3 * Dn, Dn);
    // 3: attention (ncu capture lands here)
    attn_mma_kernel<<<dim3(Sn / 128, Bn * Hn), 256, ATT_SMEM>>>(qkv, at);

    // Wo pack + GEMM (+x residual) -> fp32 out
    transpose_pack_kernel<<<dim3(32, 32), tb>>>(Wo, wo, Dn, Dn);
    mma_gemm64_kernel<<<dim3(Dn / 64, Mrows / 128), 128, GEMM64_SMEM>>>(
        at, wo, bo, x, out, Dn, Dn);

    // LN2
    ln_kernel<<<Mrows, 256>>>(out, gamma, beta, hA);

    // W1 pack + MLP1 (+GELU) -> fp16 h1
    transpose_pack_kernel<<<dim3(128, 32), tb>>>(W1, w1, Dn, D4);
    mma_gemm_kernel<true, false, false, true><<<dim3(D4 / 128, Mrows / 128), 128, GEMM_SMEM>>>(
        hA, w1, b1, x, out, h1, D4, Dn);

    // W2 pack + MLP2 (+out residual) -> fp32 out
    transpose_pack_kernel<<<dim3(32, 128), tb>>>(W2, w2, D4, Dn);
    mma_gemm64_kernel<<<dim3(Dn / 64, Mrows / 128), 128, GEMM64_SMEM>>>(
        h1, w2, b2, out, out, Dn, D4);
}

// round 15
// speedup vs baseline: 1.0273x; 1.0273x over previous
#include <cuda_runtime.h>
#include <cuda_fp16.h>
#include <cstdint>
#include <math.h>

// ----------------------------------------------------------------------------
// Problem constants
// ----------------------------------------------------------------------------
#define Bn   4
#define Sn   2048
#define Dn   1024
#define Hn   16
#define HDn  64
#define Mrows (Bn*Sn)          // 8192
#define D4   (4*Dn)            // 4096

// ----------------------------------------------------------------------------
// Scratch (device globals -- no allocations allowed)
// ----------------------------------------------------------------------------
__device__ __half g_qkv  [(size_t)Mrows * 3 * Dn];
__device__ __half g_hA   [(size_t)Mrows * Dn];
__device__ __half g_at   [(size_t)Mrows * Dn];
__device__ __half g_h1   [(size_t)Mrows * D4];
__device__ __half g_wqkvT[(size_t)3 * Dn * Dn];
__device__ __half g_woT  [(size_t)Dn * Dn];
__device__ __half g_w1T  [(size_t)D4 * Dn];
__device__ __half g_w2T  [(size_t)Dn * D4];
__device__ float  g_bp[3 * Dn];

__device__ __forceinline__ uint32_t smem_u32(const void* p) {
    uint32_t a;
    asm("{ .reg .u64 t; cvta.to.shared.u64 t, %1; cvt.u32.u64 %0, t; }" : "=r"(a) : "l"(p));
    return a;
}
__device__ __forceinline__ void cp_async16(void* dst, const void* src) {
    asm volatile("cp.async.cg.shared.global [%0], [%1], 16;"
                 :: "r"(smem_u32(dst)), "l"(src) : "memory");
}
#define CP_COMMIT() asm volatile("cp.async.commit_group;" ::: "memory")
#define CP_WAIT(n)  asm volatile("cp.async.wait_group %0;" :: "n"(n) : "memory")

__device__ __forceinline__ void ldsm_x4(uint32_t* r, uint32_t a) {
    asm volatile("ldmatrix.sync.aligned.m8n8.x4.shared.b16 {%0,%1,%2,%3}, [%4];"
                 : "=r"(r[0]), "=r"(r[1]), "=r"(r[2]), "=r"(r[3]) : "r"(a));
}
__device__ __forceinline__ void ldsm_x4_t(uint32_t* r, uint32_t a) {
    asm volatile("ldmatrix.sync.aligned.m8n8.x4.trans.shared.b16 {%0,%1,%2,%3}, [%4];"
                 : "=r"(r[0]), "=r"(r[1]), "=r"(r[2]), "=r"(r[3]) : "r"(a));
}
__device__ __forceinline__ void mma16816(float* d, const uint32_t* a, const uint32_t* b) {
    asm volatile("mma.sync.aligned.m16n8k16.row.col.f32.f16.f16.f32 "
                 "{%0,%1,%2,%3}, {%4,%5,%6,%7}, {%8,%9}, {%0,%1,%2,%3};"
                 : "+f"(d[0]), "+f"(d[1]), "+f"(d[2]), "+f"(d[3])
                 : "r"(a[0]), "r"(a[1]), "r"(a[2]), "r"(a[3]), "r"(b[0]), "r"(b[1]));
}

// ----------------------------------------------------------------------------
// Fused QKV transpose+pack (+ bias pack on z==48)
// ----------------------------------------------------------------------------
__global__ void qkv_pack_kernel(const float* __restrict__ Wq,
                                const float* __restrict__ Wk,
                                const float* __restrict__ Wv,
                                const float* __restrict__ bq,
                                const float* __restrict__ bk,
                                const float* __restrict__ bv,
                                __half* __restrict__ dst,
                                float* __restrict__ bp)
{
    __shared__ float t[32][33];
    int z = blockIdx.z;
    int tx = threadIdx.x, ty = threadIdx.y;
    if (z == 48) {
        int tid = ty * 32 + tx + blockIdx.x * 256 + blockIdx.y * 512;
        #pragma unroll
        for (int i = 0; i < 3; i++) {
            int idx = tid + i * 1024;
            if (idx < 3 * Dn) {
                int w = idx >> 10, c = idx & 1023;
                bp[idx] = (w == 0 ? bq : w == 1 ? bk : bv)[c];
            }
        }
        return;
    }
    int w = z >> 4, zh = z & 15;
    const float* src = (w == 0 ? Wq : w == 1 ? Wk : Wv) + (size_t)zh * Dn * HDn;
    int n0 = blockIdx.x * 32, k0 = blockIdx.y * 32;
    #pragma unroll
    for (int j = 0; j < 4; j++) {
        int k = k0 + ty + j * 8;
        t[ty + j * 8][tx] = src[(size_t)k * HDn + n0 + tx];
    }
    __syncthreads();
    int row_base = w * Dn + zh * HDn;
    #pragma unroll
    for (int j = 0; j < 4; j++) {
        int n = n0 + ty + j * 8;
        size_t o = (size_t)(row_base + n) * Dn + k0 + tx;
        dst[o] = __float2half_rn(t[tx][ty + j * 8]);
    }
}

// ----------------------------------------------------------------------------
// Fused Wo + W1 + W2 transpose+pack in ONE launch (9216 blocks).
//   blocks [0,1024):      Wo  [1024,1024] -> woT
//   blocks [1024,5120):   W1  [1024,4096] -> w1T
//   blocks [5120,9216):   W2  [4096,1024] -> w2T
// ----------------------------------------------------------------------------
__device__ __forceinline__ void tp32(const float* __restrict__ src,
                                     __half* __restrict__ dst,
                                     int Ks, int Ns, int bx, int by,
                                     float t[32][33], int tx, int ty)
{
    int n0 = bx * 32, k0 = by * 32;
    #pragma unroll
    for (int j = 0; j < 4; j++) {
        int k = k0 + ty + j * 8;
        t[ty + j * 8][tx] = src[(size_t)k * Ns + n0 + tx];
    }
    __syncthreads();
    #pragma unroll
    for (int j = 0; j < 4; j++) {
        int n = n0 + ty + j * 8;
        size_t o = (size_t)n * Ks + k0 + tx;
        dst[o] = __float2half_rn(t[tx][ty + j * 8]);
    }
}

__global__ void weights_pack_kernel(const float* __restrict__ Wo,
                                    const float* __restrict__ W1,
                                    const float* __restrict__ W2,
                                    __half* __restrict__ woT,
                                    __half* __restrict__ w1T,
                                    __half* __restrict__ w2T)
{
    __shared__ float t[32][33];
    int id = blockIdx.x;
    int tx = threadIdx.x, ty = threadIdx.y;
    if (id < 1024) {
        tp32(Wo, woT, Dn, Dn, id & 31, id >> 5, t, tx, ty);
    } else if (id < 5120) {
        int r = id - 1024;                 // W1: grid (128, 32)
        tp32(W1, w1T, Dn, D4, r & 127, r >> 7, t, tx, ty);
    } else {
        int r = id - 5120;                 // W2: grid (32, 128)
        tp32(W2, w2T, D4, Dn, r & 31, r >> 5, t, tx, ty);
    }
}

// ----------------------------------------------------------------------------
// LayerNorm -> fp16.
// ----------------------------------------------------------------------------
__global__ void __launch_bounds__(256) ln_kernel(const float* __restrict__ X,
                                                 const float* __restrict__ gamma,
                                                 const float* __restrict__ beta,
                                                 __half* __restrict__ Y)
{
    int row = blockIdx.x;
    int tid = threadIdx.x;
    float4 xv = ((const float4*)(X + (size_t)row * Dn))[tid];

    __shared__ float red[8];
    float s = xv.x + xv.y + xv.z + xv.w;
    #pragma unroll
    for (int o = 16; o > 0; o >>= 1) s += __shfl_xor_sync(0xffffffffu, s, o);
    if ((tid & 31) == 0) red[tid >> 5] = s;
    __syncthreads();
    float mu = (red[0]+red[1]+red[2]+red[3]+red[4]+red[5]+red[6]+red[7]) * (1.0f / Dn);
    __syncthreads();

    float dx = xv.x - mu, dy = xv.y - mu, dz = xv.z - mu, dw = xv.w - mu;
    float sq = dx*dx + dy*dy + dz*dz + dw*dw;
    #pragma unroll
    for (int o = 16; o > 0; o >>= 1) sq += __shfl_xor_sync(0xffffffffu, sq, o);
    if ((tid & 31) == 0) red[tid >> 5] = sq;
    __syncthreads();
    float var = (red[0]+red[1]+red[2]+red[3]+red[4]+red[5]+red[6]+red[7]) * (1.0f / Dn);
    float inv = rsqrtf(var + 1e-5f);

    float4 gv = ((const float4*)gamma)[tid];
    float4 bv = ((const float4*)beta)[tid];
    float o0 = dx*inv*gv.x + bv.x, o1 = dy*inv*gv.y + bv.y;
    float o2 = dz*inv*gv.z + bv.z, o3 = dw*inv*gv.w + bv.w;

    size_t off = (size_t)row * Dn + tid * 4;
    *(__half2*)&Y[off]     = __floats2half2_rn(o0, o1);
    *(__half2*)&Y[off + 2] = __floats2half2_rn(o2, o3);
}

// ----------------------------------------------------------------------------
// Raw mma.sync fp16 GEMM (R11/R13 config: 128x128 tile, 4 warps, 64x64 warp
// tile, BK=64, 2-stage, 3 CTAs/SM, smem-staged float4 epilogue).
// ----------------------------------------------------------------------------
__device__ __forceinline__ float gelu_exact(float v) {
    return 0.5f * v * (1.0f + erff(v * 0.70710678118654752f));
}

#define BK     64
#define KPITCH 72
#define TILEB  (128 * KPITCH * 2)
#define STAGEB (2 * TILEB)
#define NSTAGE 2
#define GEMM_SMEM (NSTAGE * STAGEB)
#define SPITCH 132

template <bool GELU_, bool RES_, bool OUTF, bool OUTB>
__global__ void __launch_bounds__(128, 3) mma_gemm_kernel(
    const __half* __restrict__ A, const __half* __restrict__ B,
    const float* __restrict__ bias, const float* __restrict__ residual,
    float* __restrict__ Cf, __half* __restrict__ Ch,
    int N, int K)
{
    extern __shared__ __align__(128) char smem[];
    float* stg = (float*)smem;

    const int tid = threadIdx.x;
    const int wid = tid >> 5;
    const int lane = tid & 31;
    const int wm = wid >> 1;
    const int wn = wid & 1;
    const int bx = blockIdx.x, by = blockIdx.y;

    const size_t arow = (size_t)by * 128;
    const size_t brow = (size_t)bx * 128;

    auto load_chunk = [&](int kc, int st) {
        char* base = smem + st * STAGEB;
        __half* A_s = (__half*)(base);
        __half* B_s = (__half*)(base + TILEB);
        #pragma unroll
        for (int i = 0; i < 8; i++) {
            int idx = tid + i * 128;
            int row = idx >> 3, c = idx & 7;
            int so = row * KPITCH + c * 8;
            cp_async16(&A_s[so], A + (arow + row) * (size_t)K + kc * BK + c * 8);
            cp_async16(&B_s[so], B + (brow + row) * (size_t)K + kc * BK + c * 8);
        }
    };

    float acc[4][8][4];
    #pragma unroll
    for (int i = 0; i < 4; i++)
        #pragma unroll
        for (int n = 0; n < 8; n++)
            #pragma unroll
            for (int e = 0; e < 4; e++) acc[i][n][e] = 0.0f;

    const int a_r  = wm * 64 + (lane & 15);
    const int a_k  = (lane >> 4) << 3;
    const int b_r  = wn * 64 + ((lane >> 4) << 3) + (lane & 7);
    const int b_k  = ((lane >> 3) & 1) << 3;

    const int nk = K / BK;
    load_chunk(0, 0); CP_COMMIT();

    for (int kc = 0; kc < nk; kc++) {
        const int st = kc & 1;
        CP_WAIT(0);
        __syncthreads();
        if (kc + 1 < nk) { load_chunk(kc + 1, st ^ 1); CP_COMMIT(); }

        char* base = smem + st * STAGEB;
        const uint32_t uA = smem_u32(base);
        const uint32_t uB = smem_u32(base + TILEB);

        #pragma unroll
        for (int ks = 0; ks < BK / 16; ks++) {
            const int kof = ks * 16;
            uint32_t a[4][4];
            #pragma unroll
            for (int i = 0; i < 4; i++)
                ldsm_x4(a[i], uA + (uint32_t)(((a_r + i * 16) * KPITCH + kof + a_k) * 2));
            #pragma unroll
            for (int gp = 0; gp < 2; gp++) {
                uint32_t b[2][4];
                #pragma unroll
                for (int g = 0; g < 2; g++)
                    ldsm_x4(b[g], uB + (uint32_t)(((b_r + (gp * 2 + g) * 16) * KPITCH + kof + b_k) * 2));
                #pragma unroll
                for (int i = 0; i < 4; i++)
                    #pragma unroll
                    for (int nn = 0; nn < 4; nn++)
                        mma16816(acc[i][gp * 4 + nn], a[i], &b[nn >> 1][(nn & 1) * 2]);
            }
        }
    }
    __syncthreads();

    const int c_r = lane >> 2;
    const int c_c = (lane & 3) << 1;
    #pragma unroll
    for (int i = 0; i < 4; i++)
        #pragma unroll
        for (int n = 0; n < 8; n++) {
            int r0 = wm * 64 + i * 16 + c_r;
            int c0 = wn * 64 + n * 8 + c_c;
            stg[r0 * SPITCH + c0]           = acc[i][n][0];
            stg[r0 * SPITCH + c0 + 1]       = acc[i][n][1];
            stg[(r0 + 8) * SPITCH + c0]     = acc[i][n][2];
            stg[(r0 + 8) * SPITCH + c0 + 1] = acc[i][n][3];
        }
    __syncthreads();

    const int cc = tid & 31;
    const int rg = tid >> 5;
    const int ncol = bx * 128 + cc * 4;
    float4 bb = *(const float4*)&bias[ncol];
    #pragma unroll 4
    for (int rr = 0; rr < 32; rr++) {
        int row = rg * 32 + rr;
        size_t m = arow + row;
        float4 v = *(float4*)&stg[row * SPITCH + cc * 4];
        v.x += bb.x; v.y += bb.y; v.z += bb.z; v.w += bb.w;
        if (GELU_) {
            v.x = gelu_exact(v.x); v.y = gelu_exact(v.y);
            v.z = gelu_exact(v.z); v.w = gelu_exact(v.w);
        }
        if (RES_) {
            float4 rv = *(const float4*)&residual[m * N + ncol];
            v.x += rv.x; v.y += rv.y; v.z += rv.z; v.w += rv.w;
        }
        if (OUTF) *(float4*)&Cf[m * N + ncol] = v;
        if (OUTB) {
            size_t o = m * N + ncol;
            *(__half2*)&Ch[o]     = __floats2half2_rn(v.x, v.y);
            *(__half2*)&Ch[o + 2] = __floats2half2_rn(v.z, v.w);
        }
    }
}

// ----------------------------------------------------------------------------
// 128x64-tile GEMM for N=1024 GEMMs (Wo, MLP2) -- 4 CTAs/SM (R13 version).
// Always: +bias, +residual, fp32 out. Smem-staged float4 epilogue.
// ----------------------------------------------------------------------------
#define BTILE64B (64 * KPITCH * 2)
#define STAGE64B (TILEB + BTILE64B)
#define GEMM64_SMEM (2 * STAGE64B)
#define SP64 68

__global__ void __launch_bounds__(128, 4) mma_gemm64_kernel(
    const __half* __restrict__ A, const __half* __restrict__ B,
    const float* __restrict__ bias, const float* __restrict__ residual,
    float* __restrict__ Cf, int N, int K)
{
    extern __shared__ __align__(128) char smem[];
    float* stg = (float*)smem;

    const int tid = threadIdx.x;
    const int wid = tid >> 5;
    const int lane = tid & 31;
    const int wm = wid >> 1;
    const int wn = wid & 1;
    const int bx = blockIdx.x, by = blockIdx.y;

    const size_t arow = (size_t)by * 128;
    const size_t brow = (size_t)bx * 64;

    auto load_chunk = [&](int kc, int st) {
        char* base = smem + st * STAGE64B;
        __half* A_s = (__half*)(base);
        __half* B_s = (__half*)(base + TILEB);
        #pragma unroll
        for (int i = 0; i < 8; i++) {
            int idx = tid + i * 128;
            int row = idx >> 3, c = idx & 7;
            cp_async16(&A_s[row * KPITCH + c * 8],
                       A + (arow + row) * (size_t)K + kc * BK + c * 8);
        }
        #pragma unroll
        for (int i = 0; i < 4; i++) {
            int idx = tid + i * 128;
            int row = idx >> 3, c = idx & 7;
            cp_async16(&B_s[row * KPITCH + c * 8],
                       B + (brow + row) * (size_t)K + kc * BK + c * 8);
        }
    };

    float acc[4][4][4];
    #pragma unroll
    for (int i = 0; i < 4; i++)
        #pragma unroll
        for (int n = 0; n < 4; n++)
            #pragma unroll
            for (int e = 0; e < 4; e++) acc[i][n][e] = 0.0f;

    const int a_r  = wm * 64 + (lane & 15);
    const int a_k  = (lane >> 4) << 3;
    const int b_r  = wn * 32 + ((lane >> 4) << 3) + (lane & 7);
    const int b_k  = ((lane >> 3) & 1) << 3;

    const int nk = K / BK;
    load_chunk(0, 0); CP_COMMIT();

    for (int kc = 0; kc < nk; kc++) {
        const int st = kc & 1;
        CP_WAIT(0);
        __syncthreads();
        if (kc + 1 < nk) { load_chunk(kc + 1, st ^ 1); CP_COMMIT(); }

        char* base = smem + st * STAGE64B;
        const uint32_t uA = smem_u32(base);
        const uint32_t uB = smem_u32(base + TILEB);

        #pragma unroll
        for (int ks = 0; ks < BK / 16; ks++) {
            const int kof = ks * 16;
            uint32_t a[4][4], b[2][4];
            #pragma unroll
            for (int i = 0; i < 4; i++)
                ldsm_x4(a[i], uA + (uint32_t)(((a_r + i * 16) * KPITCH + kof + a_k) * 2));
            #pragma unroll
            for (int g = 0; g < 2; g++)
                ldsm_x4(b[g], uB + (uint32_t)(((b_r + g * 16) * KPITCH + kof + b_k) * 2));
            #pragma unroll
            for (int i = 0; i < 4; i++)
                #pragma unroll
                for (int nn = 0; nn < 4; nn++)
                    mma16816(acc[i][nn], a[i], &b[nn >> 1][(nn & 1) * 2]);
        }
    }
    __syncthreads();

    const int c_r = lane >> 2;
    const int c_c = (lane & 3) << 1;
    #pragma unroll
    for (int i = 0; i < 4; i++)
        #pragma unroll
        for (int n = 0; n < 4; n++) {
            int r0 = wm * 64 + i * 16 + c_r;
            int c0 = wn * 32 + n * 8 + c_c;
            stg[r0 * SP64 + c0]           = acc[i][n][0];
            stg[r0 * SP64 + c0 + 1]       = acc[i][n][1];
            stg[(r0 + 8) * SP64 + c0]     = acc[i][n][2];
            stg[(r0 + 8) * SP64 + c0 + 1] = acc[i][n][3];
        }
    __syncthreads();

    const int cc = tid & 15;
    const int rg = tid >> 4;
    const int ncol = bx * 64 + cc * 4;
    float4 bb = *(const float4*)&bias[ncol];
    #pragma unroll 4
    for (int rr = 0; rr < 16; rr++) {
        int row = rg * 16 + rr;
        size_t m = arow + row;
        float4 v = *(float4*)&stg[row * SP64 + cc * 4];
        float4 rv = *(const float4*)&residual[m * N + ncol];
        v.x += bb.x + rv.x; v.y += bb.y + rv.y;
        v.z += bb.z + rv.z; v.w += bb.w + rv.w;
        *(float4*)&Cf[m * N + ncol] = v;
    }
}

// ----------------------------------------------------------------------------
// Tensor-core flash attention: 256 threads, 128-query tile, natural order.
// exp2-folded softmax; warp skip of fully-masked tiles; conditional o-rescale.
// ----------------------------------------------------------------------------
#define AQP 72
#define ATT_SMEM ((128 + 4 * 64) * AQP * 2)
#define C2 0.18033688011112042f    // 0.125 * log2(e)

__global__ void __launch_bounds__(256) attn_mma_kernel(const __half* __restrict__ QKV,
                                                       __half* __restrict__ O)
{
    extern __shared__ __align__(16) __half smh[];
    __half* Qs = smh;

    int qb = blockIdx.x;
    int bh = blockIdx.y;
    int b = bh >> 4, h = bh & 15;
    int tid = threadIdx.x, w = tid >> 5, lane = tid & 31;

    const size_t rowbase = (size_t)(b * Sn) * 3072 + (size_t)h * 64;

    #pragma unroll
    for (int i = 0; i < 4; i++) {
        int idx = tid + i * 256;
        int row = idx >> 3, c = idx & 7;
        cp_async16(&Qs[row * AQP + c * 8],
                   QKV + rowbase + (size_t)(qb * 128 + row) * 3072 + c * 8);
    }
    CP_COMMIT();

    auto load_kv = [&](int kb, int st) {
        __half* K_s = smh + (128 + 64 * st) * AQP;
        __half* V_s = smh + (128 + 64 * (2 + st)) * AQP;
        #pragma unroll
        for (int i = 0; i < 2; i++) {
            int idx = tid + i * 256;
            int row = idx >> 3, c = idx & 7;
            size_t src = rowbase + (size_t)(kb * 64 + row) * 3072 + c * 8;
            cp_async16(&K_s[row * AQP + c * 8], QKV + src + 1024);
            cp_async16(&V_s[row * AQP + c * 8], QKV + src + 2048);
        }
    };
    load_kv(0, 0); CP_COMMIT();
    CP_WAIT(0);
    __syncthreads();

    uint32_t aQ[4][4];
    {
        const uint32_t uQ = smem_u32(Qs);
        int a_r = w * 16 + (lane & 15);
        int a_k = (lane >> 4) << 3;
        #pragma unroll
        for (int t = 0; t < 4; t++)
            ldsm_x4(aQ[t], uQ + (uint32_t)((a_r * AQP + t * 16 + a_k) * 2));
    }

    const int bk_r = ((lane >> 4) << 3) + (lane & 7);
    const int bk_k = ((lane >> 3) & 1) << 3;
    const int bv_r = (((lane >> 3) & 1) << 3) + (lane & 7);
    const int bv_c = (lane >> 4) << 3;

    float o[8][4];
    #pragma unroll
    for (int j = 0; j < 8; j++)
        #pragma unroll
        for (int e = 0; e < 4; e++) o[j][e] = 0.0f;
    float m0 = -1e30f, m1 = -1e30f, l0 = 0.0f, l1 = 0.0f;

    const int wrow = qb * 128 + w * 16;
    const int qg0  = wrow + (lane >> 2);
    const int kb_end = 2 * qb + 1;

    for (int kb = 0; kb <= kb_end; kb++) {
        const int st = kb & 1;
        if (kb < kb_end) { load_kv(kb + 1, st ^ 1); CP_COMMIT(); }

        const bool full_skip = (kb * 64 > wrow + 15);
        if (!full_skip) {
            const uint32_t uK = smem_u32(smh + (128 + 64 * st) * AQP);
            const uint32_t uV = smem_u32(smh + (128 + 64 * (2 + st)) * AQP);

            float s[8][4];
            #pragma unroll
            for (int j = 0; j < 8; j++)
                #pragma unroll
                for (int e = 0; e < 4; e++) s[j][e] = 0.0f;
            #pragma unroll
            for (int t = 0; t < 4; t++) {
                uint32_t bK[4][4];
                #pragma unroll
                for (int g = 0; g < 4; g++)
                    ldsm_x4(bK[g], uK + (uint32_t)(((g * 16 + bk_r) * AQP + t * 16 + bk_k) * 2));
                #pragma unroll
                for (int j = 0; j < 8; j++)
                    mma16816(s[j], aQ[t], &bK[j >> 1][(j & 1) * 2]);
            }

            if (kb * 64 + 63 > wrow) {
                #pragma unroll
                for (int j = 0; j < 8; j++) {
                    int col = kb * 64 + j * 8 + (lane & 3) * 2;
                    if (col     > qg0)     s[j][0] = -1e30f;
                    if (col + 1 > qg0)     s[j][1] = -1e30f;
                    if (col     > qg0 + 8) s[j][2] = -1e30f;
                    if (col + 1 > qg0 + 8) s[j][3] = -1e30f;
                }
            }

            float ml0 = -1e30f, ml1 = -1e30f;
            #pragma unroll
            for (int j = 0; j < 8; j++) {
                ml0 = fmaxf(ml0, fmaxf(s[j][0], s[j][1]));
                ml1 = fmaxf(ml1, fmaxf(s[j][2], s[j][3]));
            }
            ml0 = fmaxf(ml0, __shfl_xor_sync(0xffffffffu, ml0, 1));
            ml0 = fmaxf(ml0, __shfl_xor_sync(0xffffffffu, ml0, 2));
            ml1 = fmaxf(ml1, __shfl_xor_sync(0xffffffffu, ml1, 1));
            ml1 = fmaxf(ml1, __shfl_xor_sync(0xffffffffu, ml1, 2));

            float mn0 = fmaxf(m0, ml0), mn1 = fmaxf(m1, ml1);
            float al0 = exp2f((m0 - mn0) * C2), al1 = exp2f((m1 - mn1) * C2);
            float mc0 = mn0 * C2, mc1 = mn1 * C2;

            float ls0 = 0.0f, ls1 = 0.0f;
            uint32_t pfrag[4][4];
            #pragma unroll
            for (int j = 0; j < 8; j++) {
                float p0 = exp2f(__fmaf_rn(s[j][0], C2, -mc0));
                float p1 = exp2f(__fmaf_rn(s[j][1], C2, -mc0));
                float p2 = exp2f(__fmaf_rn(s[j][2], C2, -mc1));
                float p3 = exp2f(__fmaf_rn(s[j][3], C2, -mc1));
                ls0 += p0 + p1; ls1 += p2 + p3;
                int t = j >> 1, hi = (j & 1) * 2;
                __half2 h01 = __floats2half2_rn(p0, p1);
                __half2 h23 = __floats2half2_rn(p2, p3);
                pfrag[t][hi]     = *(uint32_t*)&h01;
                pfrag[t][hi + 1] = *(uint32_t*)&h23;
            }
            ls0 += __shfl_xor_sync(0xffffffffu, ls0, 1);
            ls0 += __shfl_xor_sync(0xffffffffu, ls0, 2);
            ls1 += __shfl_xor_sync(0xffffffffu, ls1, 1);
            ls1 += __shfl_xor_sync(0xffffffffu, ls1, 2);

            l0 = l0 * al0 + ls0;  l1 = l1 * al1 + ls1;
            // Rescale o only if some lane's max moved (alpha != 1).
            if (__any_sync(0xffffffffu, (mn0 != m0) | (mn1 != m1))) {
                #pragma unroll
                for (int j = 0; j < 8; j++) {
                    o[j][0] *= al0; o[j][1] *= al0;
                    o[j][2] *= al1; o[j][3] *= al1;
                }
            }
            m0 = mn0; m1 = mn1;

            #pragma unroll
            for (int t = 0; t < 4; t++) {
                uint32_t bV[4][4];
                #pragma unroll
                for (int g = 0; g < 4; g++)
                    ldsm_x4_t(bV[g], uV + (uint32_t)(((t * 16 + bv_r) * AQP + g * 16 + bv_c) * 2));
                #pragma unroll
                for (int j = 0; j < 8; j++)
                    mma16816(o[j], pfrag[t], &bV[j >> 1][(j & 1) * 2]);
            }
        }

        if (kb < kb_end) CP_WAIT(0);
        __syncthreads();
    }

    float inv0 = 1.0f / l0, inv1 = 1.0f / l1;
    size_t ob = (size_t)(b * Sn + qb * 128 + w * 16 + (lane >> 2)) * Dn + h * 64;
    #pragma unroll
    for (int j = 0; j < 8; j++) {
        int col = j * 8 + (lane & 3) * 2;
        __half2 v0 = __floats2half2_rn(o[j][0] * inv0, o[j][1] * inv0);
        __half2 v1 = __floats2half2_rn(o[j][2] * inv1, o[j][3] * inv1);
        *(__half2*)&O[ob + col]           = v0;
        *(__half2*)&O[ob + 8 * Dn + col]  = v1;
    }
}

// ----------------------------------------------------------------------------
// Launch
// ----------------------------------------------------------------------------
extern "C" void kernel_launch(void* const* d_in, const int* in_sizes, int n_in,
                              void* d_out, int out_size)
{
    const float* x     = (const float*)d_in[0];
    const float* Wq    = (const float*)d_in[1];
    const float* Wk    = (const float*)d_in[2];
    const float* Wv    = (const float*)d_in[3];
    const float* bq    = (const float*)d_in[4];
    const float* bk    = (const float*)d_in[5];
    const float* bv    = (const float*)d_in[6];
    const float* Wo    = (const float*)d_in[7];
    const float* bo    = (const float*)d_in[8];
    const float* W1    = (const float*)d_in[9];
    const float* b1    = (const float*)d_in[10];
    const float* W2    = (const float*)d_in[11];
    const float* b2    = (const float*)d_in[12];
    const float* gamma = (const float*)d_in[13];
    const float* beta  = (const float*)d_in[14];
    float* out = (float*)d_out;

    float *bp;
    __half *qkv, *hA, *at, *h1, *wq, *wo, *w1, *w2;
    cudaGetSymbolAddress((void**)&qkv, g_qkv);
    cudaGetSymbolAddress((void**)&bp,  g_bp);
    cudaGetSymbolAddress((void**)&hA,  g_hA);
    cudaGetSymbolAddress((void**)&at,  g_at);
    cudaGetSymbolAddress((void**)&h1,  g_h1);
    cudaGetSymbolAddress((void**)&wq,  g_wqkvT);
    cudaGetSymbolAddress((void**)&wo,  g_woT);
    cudaGetSymbolAddress((void**)&w1,  g_w1T);
    cudaGetSymbolAddress((void**)&w2,  g_w2T);

    cudaFuncSetAttribute(mma_gemm_kernel<false, false, false, true >,
                         cudaFuncAttributeMaxDynamicSharedMemorySize, GEMM_SMEM);
    cudaFuncSetAttribute(mma_gemm_kernel<true,  false, false, true >,
                         cudaFuncAttributeMaxDynamicSharedMemorySize, GEMM_SMEM);
    cudaFuncSetAttribute(mma_gemm64_kernel,
                         cudaFuncAttributeMaxDynamicSharedMemorySize, GEMM64_SMEM);
    cudaFuncSetAttribute(attn_mma_kernel,
                         cudaFuncAttributeMaxDynamicSharedMemorySize, ATT_SMEM);

    dim3 tb(32, 8);
    // 0: fused QKV weight + bias pack
    qkv_pack_kernel<<<dim3(2, 32, 49), tb>>>(Wq, Wk, Wv, bq, bk, bv, wq, bp);
    // 1: fused Wo+W1+W2 pack (one launch)
    weights_pack_kernel<<<9216, tb>>>(Wo, W1, W2, wo, w1, w2);
    // 2: LN1
    ln_kernel<<<Mrows, 256>>>(x, gamma, beta, hA);
    // 3: QKV GEMM -> fp16 qkv (ncu capture lands here)
    mma_gemm_kernel<false, false, false, true><<<dim3(3 * Dn / 128, Mrows / 128), 128, GEMM_SMEM>>>(
        hA, wq, bp, x, out, qkv, 3 * Dn, Dn);
    // 4: attention
    attn_mma_kernel<<<dim3(Sn / 128, Bn * Hn), 256, ATT_SMEM>>>(qkv, at);
    // 5: Wo GEMM (+x residual) -> fp32 out
    mma_gemm64_kernel<<<dim3(Dn / 64, Mrows / 128), 128, GEMM64_SMEM>>>(
        at, wo, bo, x, out, Dn, Dn);
    // 6: LN2
    ln_kernel<<<Mrows, 256>>>(out, gamma, beta, hA);
    // 7: MLP1 (+GELU) -> fp16 h1
    mma_gemm_kernel<true, false, false, true><<<dim3(D4 / 128, Mrows / 128), 128, GEMM_SMEM>>>(
        hA, w1, b1, x, out, h1, D4, Dn);
    // 8: MLP2 (+out residual) -> fp32 out
    mma_gemm64_kernel<<<dim3(Dn / 64, Mrows / 128), 128, GEMM64_SMEM>>>(
        h1, w2, b2, out, out, Dn, D4);
}

// round 17
// speedup vs baseline: 1.0392x; 1.0116x over previous
#include <cuda_runtime.h>
#include <cuda_fp16.h>
#include <cstdint>
#include <math.h>

// ----------------------------------------------------------------------------
// Problem constants
// ----------------------------------------------------------------------------
#define Bn   4
#define Sn   2048
#define Dn   1024
#define Hn   16
#define HDn  64
#define Mrows (Bn*Sn)          // 8192
#define D4   (4*Dn)            // 4096

// ----------------------------------------------------------------------------
// Scratch (device globals -- no allocations allowed)
// ----------------------------------------------------------------------------
__device__ __half g_qkv  [(size_t)Mrows * 3 * Dn];
__device__ __half g_hA   [(size_t)Mrows * Dn];
__device__ __half g_at   [(size_t)Mrows * Dn];
__device__ __half g_h1   [(size_t)Mrows * D4];
__device__ __half g_wqkvT[(size_t)3 * Dn * Dn];
__device__ __half g_woT  [(size_t)Dn * Dn];
__device__ __half g_w1T  [(size_t)D4 * Dn];
__device__ __half g_w2T  [(size_t)Dn * D4];
__device__ float  g_bp[3 * Dn];

__device__ __forceinline__ uint32_t smem_u32(const void* p) {
    uint32_t a;
    asm("{ .reg .u64 t; cvta.to.shared.u64 t, %1; cvt.u32.u64 %0, t; }" : "=r"(a) : "l"(p));
    return a;
}
__device__ __forceinline__ void cp_async16(void* dst, const void* src) {
    asm volatile("cp.async.cg.shared.global [%0], [%1], 16;"
                 :: "r"(smem_u32(dst)), "l"(src) : "memory");
}
#define CP_COMMIT() asm volatile("cp.async.commit_group;" ::: "memory")
#define CP_WAIT(n)  asm volatile("cp.async.wait_group %0;" :: "n"(n) : "memory")

__device__ __forceinline__ void ldsm_x4(uint32_t* r, uint32_t a) {
    asm volatile("ldmatrix.sync.aligned.m8n8.x4.shared.b16 {%0,%1,%2,%3}, [%4];"
                 : "=r"(r[0]), "=r"(r[1]), "=r"(r[2]), "=r"(r[3]) : "r"(a));
}
__device__ __forceinline__ void ldsm_x4_t(uint32_t* r, uint32_t a) {
    asm volatile("ldmatrix.sync.aligned.m8n8.x4.trans.shared.b16 {%0,%1,%2,%3}, [%4];"
                 : "=r"(r[0]), "=r"(r[1]), "=r"(r[2]), "=r"(r[3]) : "r"(a));
}
__device__ __forceinline__ void mma16816(float* d, const uint32_t* a, const uint32_t* b) {
    asm volatile("mma.sync.aligned.m16n8k16.row.col.f32.f16.f16.f32 "
                 "{%0,%1,%2,%3}, {%4,%5,%6,%7}, {%8,%9}, {%0,%1,%2,%3};"
                 : "+f"(d[0]), "+f"(d[1]), "+f"(d[2]), "+f"(d[3])
                 : "r"(a[0]), "r"(a[1]), "r"(a[2]), "r"(a[3]), "r"(b[0]), "r"(b[1]));
}

// ----------------------------------------------------------------------------
// Fused QKV transpose+pack (+ bias pack on z==48)
// ----------------------------------------------------------------------------
__global__ void qkv_pack_kernel(const float* __restrict__ Wq,
                                const float* __restrict__ Wk,
                                const float* __restrict__ Wv,
                                const float* __restrict__ bq,
                                const float* __restrict__ bk,
                                const float* __restrict__ bv,
                                __half* __restrict__ dst,
                                float* __restrict__ bp)
{
    __shared__ float t[32][33];
    int z = blockIdx.z;
    int tx = threadIdx.x, ty = threadIdx.y;
    if (z == 48) {
        int tid = ty * 32 + tx + blockIdx.x * 256 + blockIdx.y * 512;
        #pragma unroll
        for (int i = 0; i < 3; i++) {
            int idx = tid + i * 1024;
            if (idx < 3 * Dn) {
                int w = idx >> 10, c = idx & 1023;
                bp[idx] = (w == 0 ? bq : w == 1 ? bk : bv)[c];
            }
        }
        return;
    }
    int w = z >> 4, zh = z & 15;
    const float* src = (w == 0 ? Wq : w == 1 ? Wk : Wv) + (size_t)zh * Dn * HDn;
    int n0 = blockIdx.x * 32, k0 = blockIdx.y * 32;
    #pragma unroll
    for (int j = 0; j < 4; j++) {
        int k = k0 + ty + j * 8;
        t[ty + j * 8][tx] = src[(size_t)k * HDn + n0 + tx];
    }
    __syncthreads();
    int row_base = w * Dn + zh * HDn;
    #pragma unroll
    for (int j = 0; j < 4; j++) {
        int n = n0 + ty + j * 8;
        size_t o = (size_t)(row_base + n) * Dn + k0 + tx;
        dst[o] = __float2half_rn(t[tx][ty + j * 8]);
    }
}

// ----------------------------------------------------------------------------
// Fused Wo + W1 + W2 transpose+pack in ONE launch (9216 blocks).
// ----------------------------------------------------------------------------
__device__ __forceinline__ void tp32(const float* __restrict__ src,
                                     __half* __restrict__ dst,
                                     int Ks, int Ns, int bx, int by,
                                     float t[32][33], int tx, int ty)
{
    int n0 = bx * 32, k0 = by * 32;
    #pragma unroll
    for (int j = 0; j < 4; j++) {
        int k = k0 + ty + j * 8;
        t[ty + j * 8][tx] = src[(size_t)k * Ns + n0 + tx];
    }
    __syncthreads();
    #pragma unroll
    for (int j = 0; j < 4; j++) {
        int n = n0 + ty + j * 8;
        size_t o = (size_t)n * Ks + k0 + tx;
        dst[o] = __float2half_rn(t[tx][ty + j * 8]);
    }
}

__global__ void weights_pack_kernel(const float* __restrict__ Wo,
                                    const float* __restrict__ W1,
                                    const float* __restrict__ W2,
                                    __half* __restrict__ woT,
                                    __half* __restrict__ w1T,
                                    __half* __restrict__ w2T)
{
    __shared__ float t[32][33];
    int id = blockIdx.x;
    int tx = threadIdx.x, ty = threadIdx.y;
    if (id < 1024) {
        tp32(Wo, woT, Dn, Dn, id & 31, id >> 5, t, tx, ty);
    } else if (id < 5120) {
        int r = id - 1024;
        tp32(W1, w1T, Dn, D4, r & 127, r >> 7, t, tx, ty);
    } else {
        int r = id - 5120;
        tp32(W2, w2T, D4, Dn, r & 31, r >> 5, t, tx, ty);
    }
}

// ----------------------------------------------------------------------------
// LayerNorm -> fp16.
// ----------------------------------------------------------------------------
__global__ void __launch_bounds__(256) ln_kernel(const float* __restrict__ X,
                                                 const float* __restrict__ gamma,
                                                 const float* __restrict__ beta,
                                                 __half* __restrict__ Y)
{
    int row = blockIdx.x;
    int tid = threadIdx.x;
    float4 xv = ((const float4*)(X + (size_t)row * Dn))[tid];

    __shared__ float red[8];
    float s = xv.x + xv.y + xv.z + xv.w;
    #pragma unroll
    for (int o = 16; o > 0; o >>= 1) s += __shfl_xor_sync(0xffffffffu, s, o);
    if ((tid & 31) == 0) red[tid >> 5] = s;
    __syncthreads();
    float mu = (red[0]+red[1]+red[2]+red[3]+red[4]+red[5]+red[6]+red[7]) * (1.0f / Dn);
    __syncthreads();

    float dx = xv.x - mu, dy = xv.y - mu, dz = xv.z - mu, dw = xv.w - mu;
    float sq = dx*dx + dy*dy + dz*dz + dw*dw;
    #pragma unroll
    for (int o = 16; o > 0; o >>= 1) sq += __shfl_xor_sync(0xffffffffu, sq, o);
    if ((tid & 31) == 0) red[tid >> 5] = sq;
    __syncthreads();
    float var = (red[0]+red[1]+red[2]+red[3]+red[4]+red[5]+red[6]+red[7]) * (1.0f / Dn);
    float inv = rsqrtf(var + 1e-5f);

    float4 gv = ((const float4*)gamma)[tid];
    float4 bv = ((const float4*)beta)[tid];
    float o0 = dx*inv*gv.x + bv.x, o1 = dy*inv*gv.y + bv.y;
    float o2 = dz*inv*gv.z + bv.z, o3 = dw*inv*gv.w + bv.w;

    size_t off = (size_t)row * Dn + tid * 4;
    *(__half2*)&Y[off]     = __floats2half2_rn(o0, o1);
    *(__half2*)&Y[off + 2] = __floats2half2_rn(o2, o3);
}

// ----------------------------------------------------------------------------
// Raw mma.sync fp16 GEMM (128x128 tile, 4 warps, 64x64 warp tile, BK=64,
// 2-stage, 3 CTAs/SM, smem-staged float4 epilogue). R13-validated.
// ----------------------------------------------------------------------------
__device__ __forceinline__ float gelu_exact(float v) {
    return 0.5f * v * (1.0f + erff(v * 0.70710678118654752f));
}

#define BK     64
#define KPITCH 72
#define TILEB  (128 * KPITCH * 2)
#define STAGEB (2 * TILEB)
#define NSTAGE 2
#define GEMM_SMEM (NSTAGE * STAGEB)
#define SPITCH 132

template <bool GELU_, bool RES_, bool OUTF, bool OUTB>
__global__ void __launch_bounds__(128, 3) mma_gemm_kernel(
    const __half* __restrict__ A, const __half* __restrict__ B,
    const float* __restrict__ bias, const float* __restrict__ residual,
    float* __restrict__ Cf, __half* __restrict__ Ch,
    int N, int K)
{
    extern __shared__ __align__(128) char smem[];
    float* stg = (float*)smem;

    const int tid = threadIdx.x;
    const int wid = tid >> 5;
    const int lane = tid & 31;
    const int wm = wid >> 1;
    const int wn = wid & 1;
    const int bx = blockIdx.x, by = blockIdx.y;

    const size_t arow = (size_t)by * 128;
    const size_t brow = (size_t)bx * 128;

    auto load_chunk = [&](int kc, int st) {
        char* base = smem + st * STAGEB;
        __half* A_s = (__half*)(base);
        __half* B_s = (__half*)(base + TILEB);
        #pragma unroll
        for (int i = 0; i < 8; i++) {
            int idx = tid + i * 128;
            int row = idx >> 3, c = idx & 7;
            int so = row * KPITCH + c * 8;
            cp_async16(&A_s[so], A + (arow + row) * (size_t)K + kc * BK + c * 8);
            cp_async16(&B_s[so], B + (brow + row) * (size_t)K + kc * BK + c * 8);
        }
    };

    float acc[4][8][4];
    #pragma unroll
    for (int i = 0; i < 4; i++)
        #pragma unroll
        for (int n = 0; n < 8; n++)
            #pragma unroll
            for (int e = 0; e < 4; e++) acc[i][n][e] = 0.0f;

    const int a_r  = wm * 64 + (lane & 15);
    const int a_k  = (lane >> 4) << 3;
    const int b_r  = wn * 64 + ((lane >> 4) << 3) + (lane & 7);
    const int b_k  = ((lane >> 3) & 1) << 3;

    const int nk = K / BK;
    load_chunk(0, 0); CP_COMMIT();

    for (int kc = 0; kc < nk; kc++) {
        const int st = kc & 1;
        CP_WAIT(0);
        __syncthreads();
        if (kc + 1 < nk) { load_chunk(kc + 1, st ^ 1); CP_COMMIT(); }

        char* base = smem + st * STAGEB;
        const uint32_t uA = smem_u32(base);
        const uint32_t uB = smem_u32(base + TILEB);

        #pragma unroll
        for (int ks = 0; ks < BK / 16; ks++) {
            const int kof = ks * 16;
            uint32_t a[4][4];
            #pragma unroll
            for (int i = 0; i < 4; i++)
                ldsm_x4(a[i], uA + (uint32_t)(((a_r + i * 16) * KPITCH + kof + a_k) * 2));
            #pragma unroll
            for (int gp = 0; gp < 2; gp++) {
                uint32_t b[2][4];
                #pragma unroll
                for (int g = 0; g < 2; g++)
                    ldsm_x4(b[g], uB + (uint32_t)(((b_r + (gp * 2 + g) * 16) * KPITCH + kof + b_k) * 2));
                #pragma unroll
                for (int i = 0; i < 4; i++)
                    #pragma unroll
                    for (int nn = 0; nn < 4; nn++)
                        mma16816(acc[i][gp * 4 + nn], a[i], &b[nn >> 1][(nn & 1) * 2]);
            }
        }
    }
    __syncthreads();

    const int c_r = lane >> 2;
    const int c_c = (lane & 3) << 1;
    #pragma unroll
    for (int i = 0; i < 4; i++)
        #pragma unroll
        for (int n = 0; n < 8; n++) {
            int r0 = wm * 64 + i * 16 + c_r;
            int c0 = wn * 64 + n * 8 + c_c;
            stg[r0 * SPITCH + c0]           = acc[i][n][0];
            stg[r0 * SPITCH + c0 + 1]       = acc[i][n][1];
            stg[(r0 + 8) * SPITCH + c0]     = acc[i][n][2];
            stg[(r0 + 8) * SPITCH + c0 + 1] = acc[i][n][3];
        }
    __syncthreads();

    const int cc = tid & 31;
    const int rg = tid >> 5;
    const int ncol = bx * 128 + cc * 4;
    float4 bb = *(const float4*)&bias[ncol];
    #pragma unroll 4
    for (int rr = 0; rr < 32; rr++) {
        int row = rg * 32 + rr;
        size_t m = arow + row;
        float4 v = *(float4*)&stg[row * SPITCH + cc * 4];
        v.x += bb.x; v.y += bb.y; v.z += bb.z; v.w += bb.w;
        if (GELU_) {
            v.x = gelu_exact(v.x); v.y = gelu_exact(v.y);
            v.z = gelu_exact(v.z); v.w = gelu_exact(v.w);
        }
        if (RES_) {
            float4 rv = *(const float4*)&residual[m * N + ncol];
            v.x += rv.x; v.y += rv.y; v.z += rv.z; v.w += rv.w;
        }
        if (OUTF) *(float4*)&Cf[m * N + ncol] = v;
        if (OUTB) {
            size_t o = m * N + ncol;
            *(__half2*)&Ch[o]     = __floats2half2_rn(v.x, v.y);
            *(__half2*)&Ch[o + 2] = __floats2half2_rn(v.z, v.w);
        }
    }
}

// ----------------------------------------------------------------------------
// 128x64-tile GEMM for N=1024 GEMMs (Wo, MLP2) -- 4 CTAs/SM (R13 version).
// ----------------------------------------------------------------------------
#define BTILE64B (64 * KPITCH * 2)
#define STAGE64B (TILEB + BTILE64B)
#define GEMM64_SMEM (2 * STAGE64B)
#define SP64 68

__global__ void __launch_bounds__(128, 4) mma_gemm64_kernel(
    const __half* __restrict__ A, const __half* __restrict__ B,
    const float* __restrict__ bias, const float* __restrict__ residual,
    float* __restrict__ Cf, int N, int K)
{
    extern __shared__ __align__(128) char smem[];
    float* stg = (float*)smem;

    const int tid = threadIdx.x;
    const int wid = tid >> 5;
    const int lane = tid & 31;
    const int wm = wid >> 1;
    const int wn = wid & 1;
    const int bx = blockIdx.x, by = blockIdx.y;

    const size_t arow = (size_t)by * 128;
    const size_t brow = (size_t)bx * 64;

    auto load_chunk = [&](int kc, int st) {
        char* base = smem + st * STAGE64B;
        __half* A_s = (__half*)(base);
        __half* B_s = (__half*)(base + TILEB);
        #pragma unroll
        for (int i = 0; i < 8; i++) {
            int idx = tid + i * 128;
            int row = idx >> 3, c = idx & 7;
            cp_async16(&A_s[row * KPITCH + c * 8],
                       A + (arow + row) * (size_t)K + kc * BK + c * 8);
        }
        #pragma unroll
        for (int i = 0; i < 4; i++) {
            int idx = tid + i * 128;
            int row = idx >> 3, c = idx & 7;
            cp_async16(&B_s[row * KPITCH + c * 8],
                       B + (brow + row) * (size_t)K + kc * BK + c * 8);
        }
    };

    float acc[4][4][4];
    #pragma unroll
    for (int i = 0; i < 4; i++)
        #pragma unroll
        for (int n = 0; n < 4; n++)
            #pragma unroll
            for (int e = 0; e < 4; e++) acc[i][n][e] = 0.0f;

    const int a_r  = wm * 64 + (lane & 15);
    const int a_k  = (lane >> 4) << 3;
    const int b_r  = wn * 32 + ((lane >> 4) << 3) + (lane & 7);
    const int b_k  = ((lane >> 3) & 1) << 3;

    const int nk = K / BK;
    load_chunk(0, 0); CP_COMMIT();

    for (int kc = 0; kc < nk; kc++) {
        const int st = kc & 1;
        CP_WAIT(0);
        __syncthreads();
        if (kc + 1 < nk) { load_chunk(kc + 1, st ^ 1); CP_COMMIT(); }

        char* base = smem + st * STAGE64B;
        const uint32_t uA = smem_u32(base);
        const uint32_t uB = smem_u32(base + TILEB);

        #pragma unroll
        for (int ks = 0; ks < BK / 16; ks++) {
            const int kof = ks * 16;
            uint32_t a[4][4], b[2][4];
            #pragma unroll
            for (int i = 0; i < 4; i++)
                ldsm_x4(a[i], uA + (uint32_t)(((a_r + i * 16) * KPITCH + kof + a_k) * 2));
            #pragma unroll
            for (int g = 0; g < 2; g++)
                ldsm_x4(b[g], uB + (uint32_t)(((b_r + g * 16) * KPITCH + kof + b_k) * 2));
            #pragma unroll
            for (int i = 0; i < 4; i++)
                #pragma unroll
                for (int nn = 0; nn < 4; nn++)
                    mma16816(acc[i][nn], a[i], &b[nn >> 1][(nn & 1) * 2]);
        }
    }
    __syncthreads();

    const int c_r = lane >> 2;
    const int c_c = (lane & 3) << 1;
    #pragma unroll
    for (int i = 0; i < 4; i++)
        #pragma unroll
        for (int n = 0; n < 4; n++) {
            int r0 = wm * 64 + i * 16 + c_r;
            int c0 = wn * 32 + n * 8 + c_c;
            stg[r0 * SP64 + c0]           = acc[i][n][0];
            stg[r0 * SP64 + c0 + 1]       = acc[i][n][1];
            stg[(r0 + 8) * SP64 + c0]     = acc[i][n][2];
            stg[(r0 + 8) * SP64 + c0 + 1] = acc[i][n][3];
        }
    __syncthreads();

    const int cc = tid & 15;
    const int rg = tid >> 4;
    const int ncol = bx * 64 + cc * 4;
    float4 bb = *(const float4*)&bias[ncol];
    #pragma unroll 4
    for (int rr = 0; rr < 16; rr++) {
        int row = rg * 16 + rr;
        size_t m = arow + row;
        float4 v = *(float4*)&stg[row * SP64 + cc * 4];
        float4 rv = *(const float4*)&residual[m * N + ncol];
        v.x += bb.x + rv.x; v.y += bb.y + rv.y;
        v.z += bb.z + rv.z; v.w += bb.w + rv.w;
        *(float4*)&Cf[m * N + ncol] = v;
    }
}

// ----------------------------------------------------------------------------
// Tensor-core flash attention: 256 threads, 128-query tile.
// ROW-CONSISTENT max (quad-reduced, required by mma fragment layout);
// l deferred per-lane with a single exact quad-sum at the end.
// exp2-folded softmax; warp skip of fully-masked tiles.
// ----------------------------------------------------------------------------
#define AQP 72
#define ATT_SMEM ((128 + 4 * 64) * AQP * 2)
#define C2 0.18033688011112042f    // 0.125 * log2(e)

__global__ void __launch_bounds__(256) attn_mma_kernel(const __half* __restrict__ QKV,
                                                       __half* __restrict__ O)
{
    extern __shared__ __align__(16) __half smh[];
    __half* Qs = smh;

    int qb = blockIdx.x;
    int bh = blockIdx.y;
    int b = bh >> 4, h = bh & 15;
    int tid = threadIdx.x, w = tid >> 5, lane = tid & 31;

    const size_t rowbase = (size_t)(b * Sn) * 3072 + (size_t)h * 64;

    #pragma unroll
    for (int i = 0; i < 4; i++) {
        int idx = tid + i * 256;
        int row = idx >> 3, c = idx & 7;
        cp_async16(&Qs[row * AQP + c * 8],
                   QKV + rowbase + (size_t)(qb * 128 + row) * 3072 + c * 8);
    }
    CP_COMMIT();

    auto load_kv = [&](int kb, int st) {
        __half* K_s = smh + (128 + 64 * st) * AQP;
        __half* V_s = smh + (128 + 64 * (2 + st)) * AQP;
        #pragma unroll
        for (int i = 0; i < 2; i++) {
            int idx = tid + i * 256;
            int row = idx >> 3, c = idx & 7;
            size_t src = rowbase + (size_t)(kb * 64 + row) * 3072 + c * 8;
            cp_async16(&K_s[row * AQP + c * 8], QKV + src + 1024);
            cp_async16(&V_s[row * AQP + c * 8], QKV + src + 2048);
        }
    };
    load_kv(0, 0); CP_COMMIT();
    CP_WAIT(0);
    __syncthreads();

    uint32_t aQ[4][4];
    {
        const uint32_t uQ = smem_u32(Qs);
        int a_r = w * 16 + (lane & 15);
        int a_k = (lane >> 4) << 3;
        #pragma unroll
        for (int t = 0; t < 4; t++)
            ldsm_x4(aQ[t], uQ + (uint32_t)((a_r * AQP + t * 16 + a_k) * 2));
    }

    const int bk_r = ((lane >> 4) << 3) + (lane & 7);
    const int bk_k = ((lane >> 3) & 1) << 3;
    const int bv_r = (((lane >> 3) & 1) << 3) + (lane & 7);
    const int bv_c = (lane >> 4) << 3;

    float o[8][4];
    #pragma unroll
    for (int j = 0; j < 8; j++)
        #pragma unroll
        for (int e = 0; e < 4; e++) o[j][e] = 0.0f;
    float m0 = -1e30f, m1 = -1e30f;   // row-consistent running max
    float l0 = 0.0f, l1 = 0.0f;       // per-LANE partial sums (same scale)

    const int wrow = qb * 128 + w * 16;
    const int qg0  = wrow + (lane >> 2);
    const int kb_end = 2 * qb + 1;

    for (int kb = 0; kb <= kb_end; kb++) {
        const int st = kb & 1;
        if (kb < kb_end) { load_kv(kb + 1, st ^ 1); CP_COMMIT(); }

        const bool full_skip = (kb * 64 > wrow + 15);
        if (!full_skip) {
            const uint32_t uK = smem_u32(smh + (128 + 64 * st) * AQP);
            const uint32_t uV = smem_u32(smh + (128 + 64 * (2 + st)) * AQP);

            float s[8][4];
            #pragma unroll
            for (int j = 0; j < 8; j++)
                #pragma unroll
                for (int e = 0; e < 4; e++) s[j][e] = 0.0f;
            #pragma unroll
            for (int t = 0; t < 4; t++) {
                uint32_t bK[4][4];
                #pragma unroll
                for (int g = 0; g < 4; g++)
                    ldsm_x4(bK[g], uK + (uint32_t)(((g * 16 + bk_r) * AQP + t * 16 + bk_k) * 2));
                #pragma unroll
                for (int j = 0; j < 8; j++)
                    mma16816(s[j], aQ[t], &bK[j >> 1][(j & 1) * 2]);
            }

            if (kb * 64 + 63 > wrow) {
                #pragma unroll
                for (int j = 0; j < 8; j++) {
                    int col = kb * 64 + j * 8 + (lane & 3) * 2;
                    if (col     > qg0)     s[j][0] = -1e30f;
                    if (col + 1 > qg0)     s[j][1] = -1e30f;
                    if (col     > qg0 + 8) s[j][2] = -1e30f;
                    if (col + 1 > qg0 + 8) s[j][3] = -1e30f;
                }
            }

            // quad-reduced row max (REQUIRED for fragment-consistent P scale)
            float ml0 = -1e30f, ml1 = -1e30f;
            #pragma unroll
            for (int j = 0; j < 8; j++) {
                ml0 = fmaxf(ml0, fmaxf(s[j][0], s[j][1]));
                ml1 = fmaxf(ml1, fmaxf(s[j][2], s[j][3]));
            }
            ml0 = fmaxf(ml0, __shfl_xor_sync(0xffffffffu, ml0, 1));
            ml0 = fmaxf(ml0, __shfl_xor_sync(0xffffffffu, ml0, 2));
            ml1 = fmaxf(ml1, __shfl_xor_sync(0xffffffffu, ml1, 1));
            ml1 = fmaxf(ml1, __shfl_xor_sync(0xffffffffu, ml1, 2));

            float mn0 = fmaxf(m0, ml0), mn1 = fmaxf(m1, ml1);
            float al0 = exp2f((m0 - mn0) * C2), al1 = exp2f((m1 - mn1) * C2);
            float mc0 = mn0 * C2, mc1 = mn1 * C2;

            float ls0 = 0.0f, ls1 = 0.0f;
            uint32_t pfrag[4][4];
            #pragma unroll
            for (int j = 0; j < 8; j++) {
                float p0 = exp2f(__fmaf_rn(s[j][0], C2, -mc0));
                float p1 = exp2f(__fmaf_rn(s[j][1], C2, -mc0));
                float p2 = exp2f(__fmaf_rn(s[j][2], C2, -mc1));
                float p3 = exp2f(__fmaf_rn(s[j][3], C2, -mc1));
                ls0 += p0 + p1; ls1 += p2 + p3;
                int t = j >> 1, hi = (j & 1) * 2;
                __half2 h01 = __floats2half2_rn(p0, p1);
                __half2 h23 = __floats2half2_rn(p2, p3);
                pfrag[t][hi]     = *(uint32_t*)&h01;
                pfrag[t][hi + 1] = *(uint32_t*)&h23;
            }
            // NO lsum shuffles here: alpha is row-consistent, so per-lane
            // partials stay in the same scale and add exactly at the end.
            l0 = l0 * al0 + ls0;  l1 = l1 * al1 + ls1;
            m0 = mn0;             m1 = mn1;
            #pragma unroll
            for (int j = 0; j < 8; j++) {
                o[j][0] *= al0; o[j][1] *= al0;
                o[j][2] *= al1; o[j][3] *= al1;
            }

            #pragma unroll
            for (int t = 0; t < 4; t++) {
                uint32_t bV[4][4];
                #pragma unroll
                for (int g = 0; g < 4; g++)
                    ldsm_x4_t(bV[g], uV + (uint32_t)(((t * 16 + bv_r) * AQP + g * 16 + bv_c) * 2));
                #pragma unroll
                for (int j = 0; j < 8; j++)
                    mma16816(o[j], pfrag[t], &bV[j >> 1][(j & 1) * 2]);
            }
        }

        if (kb < kb_end) CP_WAIT(0);
        __syncthreads();
    }

    // Final exact quad-sum of per-lane l partials (same scale per row).
    l0 += __shfl_xor_sync(0xffffffffu, l0, 1);
    l0 += __shfl_xor_sync(0xffffffffu, l0, 2);
    l1 += __shfl_xor_sync(0xffffffffu, l1, 1);
    l1 += __shfl_xor_sync(0xffffffffu, l1, 2);
    float inv0 = 1.0f / l0, inv1 = 1.0f / l1;

    size_t ob = (size_t)(b * Sn + qb * 128 + w * 16 + (lane >> 2)) * Dn + h * 64;
    #pragma unroll
    for (int j = 0; j < 8; j++) {
        int col = j * 8 + (lane & 3) * 2;
        __half2 v0 = __floats2half2_rn(o[j][0] * inv0, o[j][1] * inv0);
        __half2 v1 = __floats2half2_rn(o[j][2] * inv1, o[j][3] * inv1);
        *(__half2*)&O[ob + col]           = v0;
        *(__half2*)&O[ob + 8 * Dn + col]  = v1;
    }
}

// ----------------------------------------------------------------------------
// Launch
// ----------------------------------------------------------------------------
extern "C" void kernel_launch(void* const* d_in, const int* in_sizes, int n_in,
                              void* d_out, int out_size)
{
    const float* x     = (const float*)d_in[0];
    const float* Wq    = (const float*)d_in[1];
    const float* Wk    = (const float*)d_in[2];
    const float* Wv    = (const float*)d_in[3];
    const float* bq    = (const float*)d_in[4];
    const float* bk    = (const float*)d_in[5];
    const float* bv    = (const float*)d_in[6];
    const float* Wo    = (const float*)d_in[7];
    const float* bo    = (const float*)d_in[8];
    const float* W1    = (const float*)d_in[9];
    const float* b1    = (const float*)d_in[10];
    const float* W2    = (const float*)d_in[11];
    const float* b2    = (const float*)d_in[12];
    const float* gamma = (const float*)d_in[13];
    const float* beta  = (const float*)d_in[14];
    float* out = (float*)d_out;

    float *bp;
    __half *qkv, *hA, *at, *h1, *wq, *wo, *w1, *w2;
    cudaGetSymbolAddress((void**)&qkv, g_qkv);
    cudaGetSymbolAddress((void**)&bp,  g_bp);
    cudaGetSymbolAddress((void**)&hA,  g_hA);
    cudaGetSymbolAddress((void**)&at,  g_at);
    cudaGetSymbolAddress((void**)&h1,  g_h1);
    cudaGetSymbolAddress((void**)&wq,  g_wqkvT);
    cudaGetSymbolAddress((void**)&wo,  g_woT);
    cudaGetSymbolAddress((void**)&w1,  g_w1T);
    cudaGetSymbolAddress((void**)&w2,  g_w2T);

    cudaFuncSetAttribute(mma_gemm_kernel<false, false, false, true >,
                         cudaFuncAttributeMaxDynamicSharedMemorySize, GEMM_SMEM);
    cudaFuncSetAttribute(mma_gemm_kernel<true,  false, false, true >,
                         cudaFuncAttributeMaxDynamicSharedMemorySize, GEMM_SMEM);
    cudaFuncSetAttribute(mma_gemm64_kernel,
                         cudaFuncAttributeMaxDynamicSharedMemorySize, GEMM64_SMEM);
    cudaFuncSetAttribute(attn_mma_kernel,
                         cudaFuncAttributeMaxDynamicSharedMemorySize, ATT_SMEM);

    dim3 tb(32, 8);
    // 0: fused QKV weight + bias pack
    qkv_pack_kernel<<<dim3(2, 32, 49), tb>>>(Wq, Wk, Wv, bq, bk, bv, wq, bp);
    // 1: fused Wo+W1+W2 pack
    weights_pack_kernel<<<9216, tb>>>(Wo, W1, W2, wo, w1, w2);
    // 2: LN1
    ln_kernel<<<Mrows, 256>>>(x, gamma, beta, hA);
    // 3: QKV GEMM -> fp16 qkv
    mma_gemm_kernel<false, false, false, true><<<dim3(3 * Dn / 128, Mrows / 128), 128, GEMM_SMEM>>>(
        hA, wq, bp, x, out, qkv, 3 * Dn, Dn);
    // 4: attention
    attn_mma_kernel<<<dim3(Sn / 128, Bn * Hn), 256, ATT_SMEM>>>(qkv, at);
    // 5: Wo GEMM (+x residual) -> fp32 out
    mma_gemm64_kernel<<<dim3(Dn / 64, Mrows / 128), 128, GEMM64_SMEM>>>(
        at, wo, bo, x, out, Dn, Dn);
    // 6: LN2
    ln_kernel<<<Mrows, 256>>>(out, gamma, beta, hA);
    // 7: MLP1 (+GELU) -> fp16 h1
    mma_gemm_kernel<true, false, false, true><<<dim3(D4 / 128, Mrows / 128), 128, GEMM_SMEM>>>(
        hA, w1, b1, x, out, h1, D4, Dn);
    // 8: MLP2 (+out residual) -> fp32 out
    mma_gemm64_kernel<<<dim3(Dn / 64, Mrows / 128), 128, GEMM64_SMEM>>>(
        h1, w2, b2, out, out, Dn, D4);
}